// round 4
// baseline (speedup 1.0000x reference)
#include <cuda_runtime.h>
#include <cuda_fp16.h>
#include <cstdint>

// Problem shape (fixed by setup_inputs)
#define M_DIM 2048
#define K_DIM 4096
#define N_DIM 11008
#define NPACK (N_DIM / 8)      // 1376
#define GROUP 128

// ---------------------------------------------------------------------------
// Scratch (device globals; allocation-free per harness rules)
// ---------------------------------------------------------------------------
__device__ __half g_A[(size_t)M_DIM * K_DIM];   // x in fp16, [M, K] row-major
__device__ __half g_B[(size_t)N_DIM * K_DIM];   // W^T in fp16, [N, K] K-major

// ---------------------------------------------------------------------------
// Kernel 1: x fp32 -> fp16
// ---------------------------------------------------------------------------
__global__ void k_convert_x(const float* __restrict__ x) {
    size_t i = ((size_t)blockIdx.x * 256 + threadIdx.x) * 4;
    float4 v = *(const float4*)(x + i);
    union { __half2 h[2]; uint2 u; } t;
    t.h[0] = __floats2half2_rn(v.x, v.y);
    t.h[1] = __floats2half2_rn(v.z, v.w);
    *(uint2*)(g_A + i) = t.u;
}

// ---------------------------------------------------------------------------
// Kernel 2: AWQ dequant + transpose -> g_B [N, K] fp16 K-major
// Block tile: 64 K x 256 N (never crosses a group boundary: 64 | 128)
// ---------------------------------------------------------------------------
__global__ void k_dequant(const int* __restrict__ qw, const int* __restrict__ qz,
                          const float* __restrict__ sc) {
    __shared__ __half tile[64 * 264];   // [k][n] with +8 halfs row pad
    const int t = threadIdx.x;
    const int k0 = blockIdx.x * 64;
    const int n0 = blockIdx.y * 256;
    const int pack = t & 31;            // n-pack within tile (32 packs of 8)
    const int kk = t >> 5;              // 0..7
    const int g = k0 >> 7;              // group index (constant per block)
    const int SH[8] = {0, 16, 4, 20, 8, 24, 12, 28};  // AWQ inverse-order shifts

    float s[8], zs[8];
    unsigned z32 = (unsigned)qz[(size_t)g * NPACK + (n0 >> 3) + pack];
#pragma unroll
    for (int m = 0; m < 8; m++) {
        s[m]  = sc[(size_t)g * N_DIM + n0 + pack * 8 + m];
        zs[m] = (float)((z32 >> SH[m]) & 15) * s[m];
    }
#pragma unroll
    for (int i = 0; i < 8; i++) {
        int k = kk * 8 + i;
        unsigned q32 = (unsigned)qw[(size_t)(k0 + k) * NPACK + (n0 >> 3) + pack];
        __align__(16) __half h[8];
#pragma unroll
        for (int m = 0; m < 8; m++)
            h[m] = __float2half((float)((q32 >> SH[m]) & 15) * s[m] - zs[m]);
        *(uint4*)&tile[k * 264 + pack * 8] = *(const uint4*)h;
    }
    __syncthreads();

    // transpose out: thread t owns row n = n0 + t, writes 64 contiguous K halfs
    const __half* col = tile + t;
    __half* dst = g_B + (size_t)(n0 + t) * K_DIM + k0;
#pragma unroll
    for (int ib = 0; ib < 8; ib++) {
        __align__(16) __half h[8];
#pragma unroll
        for (int j = 0; j < 8; j++) h[j] = col[(ib * 8 + j) * 264];
        *(uint4*)(dst + ib * 8) = *(const uint4*)h;
    }
}

// ---------------------------------------------------------------------------
// Kernel 3: fp16 mma.sync GEMM (legacy HMMA path — works on plain sm_100)
//   Tile 128(M) x 128(N), BK=64, 3-stage cp.async pipeline
//   8 warps: 2(M) x 4(N), warp tile 64x32, 4x4 m16n8k16 fragments
// ---------------------------------------------------------------------------
#define BM 128
#define BN 128
#define BK 64
#define NCHUNK (K_DIM / BK)            // 64
#define STAGES 3
#define STAGE_BYTES 32768              // A 16KB + B 16KB
#define SB_OFF 16384
#define SMEM_TOTAL (STAGES * STAGE_BYTES)   // 98304

__device__ __forceinline__ uint32_t smem_u32(const void* p) {
    uint32_t r;
    asm("{ .reg .u64 t; cvta.to.shared.u64 t, %1; cvt.u32.u64 %0, t; }"
        : "=r"(r) : "l"(p));
    return r;
}

__device__ __forceinline__ void cp16(uint32_t s, const void* g) {
    asm volatile("cp.async.cg.shared.global [%0], [%1], 16;" :: "r"(s), "l"(g));
}

__device__ __forceinline__ void ldsm_x4(uint32_t& r0, uint32_t& r1,
                                        uint32_t& r2, uint32_t& r3, uint32_t a) {
    asm volatile("ldmatrix.sync.aligned.m8n8.x4.shared.b16 {%0,%1,%2,%3}, [%4];"
                 : "=r"(r0), "=r"(r1), "=r"(r2), "=r"(r3) : "r"(a));
}

__device__ __forceinline__ void mma16816(float* c, const uint32_t* a,
                                         const uint32_t* b) {
    asm volatile(
        "mma.sync.aligned.m16n8k16.row.col.f32.f16.f16.f32 "
        "{%0,%1,%2,%3}, {%4,%5,%6,%7}, {%8,%9}, {%0,%1,%2,%3};"
        : "+f"(c[0]), "+f"(c[1]), "+f"(c[2]), "+f"(c[3])
        : "r"(a[0]), "r"(a[1]), "r"(a[2]), "r"(a[3]), "r"(b[0]), "r"(b[1]));
}

__global__ void __launch_bounds__(256) k_gemm(float* __restrict__ out) {
    extern __shared__ __align__(128) char smem[];
    const uint32_t sbase = smem_u32(smem);
    const int tid = threadIdx.x, wid = tid >> 5, lid = tid & 31;
    const int wm = wid & 1, wn = wid >> 1;      // warp grid 2(M) x 4(N)
    const int m0 = blockIdx.x * BM;
    const int n0 = blockIdx.y * BN;

    const __half* Abase = g_A + (size_t)m0 * K_DIM;
    const __half* Bbase = g_B + (size_t)n0 * K_DIM;

    // per-thread load coords (4 x 16B chunks per operand per stage)
    const int lrow = tid >> 3;                   // 0..31
    const int lc   = tid & 7;                    // 16B chunk in 128B row

    float acc[4][4][4];
#pragma unroll
    for (int i = 0; i < 4; i++)
#pragma unroll
        for (int j = 0; j < 4; j++)
#pragma unroll
            for (int c = 0; c < 4; c++) acc[i][j][c] = 0.f;

    auto load_stage = [&](int kc, int st) {
        const uint32_t sa = sbase + st * STAGE_BYTES;
        const __half* ga = Abase + kc * BK;
        const __half* gb = Bbase + kc * BK;
#pragma unroll
        for (int p = 0; p < 4; p++) {
            int row = p * 32 + lrow;
            uint32_t bo = (uint32_t)row * 128 + ((lc ^ (row & 7)) * 16);
            cp16(sa + bo,          ga + (size_t)row * K_DIM + lc * 8);
            cp16(sa + SB_OFF + bo, gb + (size_t)row * K_DIM + lc * 8);
        }
    };

    // prologue: stages 0 and 1
    load_stage(0, 0);
    asm volatile("cp.async.commit_group;" ::: "memory");
    load_stage(1, 1);
    asm volatile("cp.async.commit_group;" ::: "memory");

    for (int kc = 0; kc < NCHUNK; kc++) {
        if (kc + 2 < NCHUNK) load_stage(kc + 2, (kc + 2) % STAGES);
        asm volatile("cp.async.commit_group;" ::: "memory");   // may be empty
        asm volatile("cp.async.wait_group 2;" ::: "memory");
        __syncthreads();

        const uint32_t sa = sbase + (kc % STAGES) * STAGE_BYTES;
        const uint32_t sb = sa + SB_OFF;

#pragma unroll
        for (int ks = 0; ks < 4; ks++) {
            uint32_t a[4][4];
#pragma unroll
            for (int mf = 0; mf < 4; mf++) {
                int row = wm * 64 + mf * 16 + (lid & 15);
                int ch  = ks * 2 + (lid >> 4);
                ldsm_x4(a[mf][0], a[mf][1], a[mf][2], a[mf][3],
                        sa + (uint32_t)row * 128 + ((ch ^ (row & 7)) * 16));
            }
            uint32_t b[4][2];
#pragma unroll
            for (int p = 0; p < 2; p++) {
                int n  = wn * 32 + p * 16 + (lid >> 4) * 8 + (lid & 7);
                int ch = ks * 2 + ((lid >> 3) & 1);
                uint32_t r0, r1, r2, r3;
                ldsm_x4(r0, r1, r2, r3,
                        sb + (uint32_t)n * 128 + ((ch ^ (n & 7)) * 16));
                b[2 * p][0] = r0; b[2 * p][1] = r1;
                b[2 * p + 1][0] = r2; b[2 * p + 1][1] = r3;
            }
#pragma unroll
            for (int mf = 0; mf < 4; mf++)
#pragma unroll
                for (int nf = 0; nf < 4; nf++)
                    mma16816(acc[mf][nf], a[mf], b[nf]);
        }
        __syncthreads();
    }

    // epilogue: direct stores; thread quad covers a contiguous 32B sector
    const int qr = lid >> 2;           // 0..7
    const int qc = (lid & 3) * 2;      // 0,2,4,6
#pragma unroll
    for (int mf = 0; mf < 4; mf++) {
        int mrow = m0 + wm * 64 + mf * 16 + qr;
        float* o0 = out + (size_t)mrow * N_DIM + n0 + wn * 32 + qc;
        float* o1 = out + (size_t)(mrow + 8) * N_DIM + n0 + wn * 32 + qc;
#pragma unroll
        for (int nf = 0; nf < 4; nf++) {
            *(float2*)(o0 + nf * 8) = make_float2(acc[mf][nf][0], acc[mf][nf][1]);
            *(float2*)(o1 + nf * 8) = make_float2(acc[mf][nf][2], acc[mf][nf][3]);
        }
    }
}

// ---------------------------------------------------------------------------
// Entry point
// ---------------------------------------------------------------------------
extern "C" void kernel_launch(void* const* d_in, const int* in_sizes, int n_in,
                              void* d_out, int out_size) {
    (void)in_sizes; (void)n_in; (void)out_size;
    const float* x  = (const float*)d_in[0];
    const int*   qw = (const int*)d_in[1];
    const int*   qz = (const int*)d_in[2];
    const float* sc = (const float*)d_in[3];
    float* out = (float*)d_out;

    (void)cudaFuncSetAttribute(k_gemm, cudaFuncAttributeMaxDynamicSharedMemorySize,
                               SMEM_TOTAL);

    k_convert_x<<<(M_DIM * (size_t)K_DIM) / 1024, 256>>>(x);
    k_dequant<<<dim3(K_DIM / 64, N_DIM / 256), 256>>>(qw, qz, sc);
    k_gemm<<<dim3(M_DIM / BM, N_DIM / BN), 256, SMEM_TOTAL>>>(out);
}